// round 8
// baseline (speedup 1.0000x reference)
#include <cuda_runtime.h>

// Problem geometry (fixed by the reference)
#define WIDTH   1000
#define HEIGHT  1000
#define PS      5
#define NT      10
#define PPR     (WIDTH / PS)          // 200 patches per patch-row
#define NPIX    (WIDTH * HEIGHT)      // 1,000,000

constexpr int PATCHES_PER_BLOCK = 25;
constexpr int COLS_PER_BLOCK    = PATCHES_PER_BLOCK * PS;   // 125
constexpr int SEGS              = WIDTH / COLS_PER_BLOCK;   // 8
constexpr int THREADS           = 128;
constexpr int COEF_PER_PATCH    = 3 * NT * 2;               // 60 floats = 240 B
constexpr int MAXP_PER_WARP     = 8;                        // patches touched by one warp

using ull = unsigned long long;

// Packed dual-FMA on the f32x2 pipe (ptxas never auto-fuses this).
__device__ __forceinline__ ull fma2(ull a, ull b, ull c) {
    ull d;
    asm("fma.rn.f32x2 %0, %1, %2, %3;" : "=l"(d) : "l"(a), "l"(b), "l"(c));
    return d;
}
__device__ __forceinline__ void unpack2(ull h, float& lo, float& hi) {
    asm("mov.b64 {%0, %1}, %2;" : "=f"(lo), "=f"(hi) : "l"(h));
}
__device__ __forceinline__ void cp_async16(void* smem_dst, const void* gmem_src) {
    unsigned saddr = (unsigned)__cvta_generic_to_shared(smem_dst);
    asm volatile("cp.async.cg.shared.global [%0], [%1], 16;" :: "r"(saddr), "l"(gmem_src));
}

__global__ __launch_bounds__(THREADS, 10)   // cap regs ~48 -> whole grid resident in 1 wave
void ts_approx_kernel(const float* __restrict__ pix,     // [NPIX, 2]
                      const float* __restrict__ coef,    // [NPATCH, 3, NT, 2]
                      const float* __restrict__ bias,    // [NPATCH, 3]
                      float* __restrict__ out)           // [3, NPIX]
{
    // Per-warp private staging regions: 4 warps x 8 patches x 240B = 7680 B.
    __shared__ float s_coef[4][MAXP_PER_WARP * COEF_PER_PATCH];

    const int b    = blockIdx.x;
    const int pr   = b / SEGS;                    // patch-row 0..199
    const int seg  = b % SEGS;                    // 0..7
    const int row0 = pr * PS;
    const int c    = threadIdx.x;                 // 0..124 active
    const int w    = c >> 5;
    const int lane = c & 31;

    const int patch0 = pr * PPR + seg * PATCHES_PER_BLOCK;  // block's first patch

    // ── Pixel loads first: their DRAM latency overlaps the staging below.
    const int n0 = row0 * WIDTH + seg * COLS_PER_BLOCK + c;
    const ull* __restrict__ pixq = reinterpret_cast<const ull*>(pix);
    ull xy[PS];
    if (c < COLS_PER_BLOCK) {
        #pragma unroll
        for (int r = 0; r < PS; r++)
            xy[r] = __ldcs(&pixq[n0 + r * WIDTH]);
    }

    // ── Per-warp coefficient staging: warp w touches patches [p0w, pend].
    //    Boundary patches staged by two warps write identical bytes (benign).
    const int p0w  = (32 * w) / 5;
    const int pend = min((32 * w + 31) / 5, PATCHES_PER_BLOCK - 1);
    const int nv   = (pend - p0w + 1) * 15;       // float4 count (<= 120)
    {
        const float4* gc = reinterpret_cast<const float4*>(
            coef + (size_t)(patch0 + p0w) * COEF_PER_PATCH);
        float4* sc = reinterpret_cast<float4*>(s_coef[w]);
        #pragma unroll
        for (int i = lane; i < MAXP_PER_WARP * 15; i += 32)   // 4 fixed iterations
            if (i < nv) cp_async16(sc + i, gc + i);
        asm volatile("cp.async.commit_group;\n cp.async.wait_group 0;" ::: "memory");
    }
    __syncwarp();    // only intra-warp sync needed: no __syncthreads anywhere

    if (c >= COLS_PER_BLOCK) return;

    const int pl   = c / PS;                      // local patch 0..24
    const int slot = pl - p0w;                    // warp-local patch slot 0..7

    #pragma unroll
    for (int ch = 0; ch < 3; ch++) {
        // 5 x 16B smem loads; lane stride 240B -> conflict-free.
        const ulonglong2* cfc =
            reinterpret_cast<const ulonglong2*>(s_coef[w]) + slot * 15 + ch * 5;
        const ulonglong2 u0 = cfc[0];   // (c0, c1) pairs (a_t, b_t)
        const ulonglong2 u1 = cfc[1];
        const ulonglong2 u2 = cfc[2];
        const ulonglong2 u3 = cfc[3];
        const ulonglong2 u4 = cfc[4];
        const float bch = __ldg(&bias[(patch0 + pl) * 3 + ch]);  // 5-lane L1 broadcast

        // 5 independent packed Horner chains (one per row) -> ILP 5.
        #pragma unroll
        for (int r = 0; r < PS; r++) {
            ull h = u4.y;                  // (a9, b9)
            h = fma2(h, xy[r], u4.x);
            h = fma2(h, xy[r], u3.y);
            h = fma2(h, xy[r], u3.x);
            h = fma2(h, xy[r], u2.y);
            h = fma2(h, xy[r], u2.x);
            h = fma2(h, xy[r], u1.y);
            h = fma2(h, xy[r], u1.x);
            h = fma2(h, xy[r], u0.y);
            h = fma2(h, xy[r], u0.x);      // + (a0, b0)
            float hx, hy;
            unpack2(h, hx, hy);
            __stcs(&out[(size_t)ch * NPIX + n0 + r * WIDTH], hx + (hy + bch));
        }
    }
}

extern "C" void kernel_launch(void* const* d_in, const int* in_sizes, int n_in,
                              void* d_out, int out_size)
{
    const float* pix  = (const float*)d_in[0];   // [1e6, 2]
    const float* coef = (const float*)d_in[1];   // [40000, 3, 10, 2]
    const float* bias = (const float*)d_in[2];   // [40000, 3]
    float* out        = (float*)d_out;           // [3, 1e6]

    const int nblocks = (HEIGHT / PS) * SEGS;    // 200 * 8 = 1600
    ts_approx_kernel<<<nblocks, THREADS>>>(pix, coef, bias, out);
}

// round 9
// speedup vs baseline: 1.0669x; 1.0669x over previous
#include <cuda_runtime.h>

// Problem geometry (fixed by the reference)
#define WIDTH   1000
#define HEIGHT  1000
#define PS      5
#define NT      10
#define PPR     (WIDTH / PS)          // 200 patches per patch-row
#define NPIX    (WIDTH * HEIGHT)      // 1,000,000

constexpr int PATCHES_PER_BLOCK = 25;
constexpr int COLS_PER_BLOCK    = PATCHES_PER_BLOCK * PS;   // 125
constexpr int SEGS              = WIDTH / COLS_PER_BLOCK;   // 8
constexpr int THREADS           = 128;
constexpr int COEF_PER_PATCH    = 3 * NT * 2;               // 60 floats = 240 B
constexpr int COEF_VEC16        = PATCHES_PER_BLOCK * COEF_PER_PATCH / 4; // 375

using ull = unsigned long long;

// Packed dual-FMA on the f32x2 pipe (ptxas never auto-fuses this).
__device__ __forceinline__ ull fma2(ull a, ull b, ull c) {
    ull d;
    asm("fma.rn.f32x2 %0, %1, %2, %3;" : "=l"(d) : "l"(a), "l"(b), "l"(c));
    return d;
}
__device__ __forceinline__ void unpack2(ull h, float& lo, float& hi) {
    asm("mov.b64 {%0, %1}, %2;" : "=f"(lo), "=f"(hi) : "l"(h));
}
__device__ __forceinline__ void cp_async16(void* smem_dst, const void* gmem_src) {
    unsigned saddr = (unsigned)__cvta_generic_to_shared(smem_dst);
    asm volatile("cp.async.cg.shared.global [%0], [%1], 16;" :: "r"(saddr), "l"(gmem_src));
}
__device__ __forceinline__ void cp_async8(void* smem_dst, const void* gmem_src) {
    unsigned saddr = (unsigned)__cvta_generic_to_shared(smem_dst);
    asm volatile("cp.async.ca.shared.global [%0], [%1], 8;" :: "r"(saddr), "l"(gmem_src));
}
__device__ __forceinline__ void cp_async4(void* smem_dst, const void* gmem_src) {
    unsigned saddr = (unsigned)__cvta_generic_to_shared(smem_dst);
    asm volatile("cp.async.ca.shared.global [%0], [%1], 4;" :: "r"(saddr), "l"(gmem_src));
}

__global__ __launch_bounds__(THREADS, 10)
void ts_approx_kernel(const float* __restrict__ pix,     // [NPIX, 2]
                      const float* __restrict__ coef,    // [NPATCH, 3, NT, 2]
                      const float* __restrict__ bias,    // [NPATCH, 3]
                      float* __restrict__ out)           // [3, NPIX]
{
    __shared__ float s_coef[PATCHES_PER_BLOCK * COEF_PER_PATCH]; // 6000 B
    __shared__ ull   s_pix[PS][THREADS];                         // 5120 B (125 used/row)
    __shared__ float s_bias[PATCHES_PER_BLOCK * 3];              // 300 B

    const int b    = blockIdx.x;
    const int pr   = b / SEGS;                    // patch-row 0..199
    const int seg  = b % SEGS;                    // 0..7
    const int row0 = pr * PS;
    const int c    = threadIdx.x;                 // 0..124 active for compute
    const int patch0 = pr * PPR + seg * PATCHES_PER_BLOCK;
    const int n0   = row0 * WIDTH + seg * COLS_PER_BLOCK + c;

    // ── Stage EVERYTHING via cp.async: zero register LDGs (MLP_p1 = 0).
    // Pixels: one 8B pair per thread per row.
    const ull* __restrict__ pixq = reinterpret_cast<const ull*>(pix);
    if (c < COLS_PER_BLOCK) {
        #pragma unroll
        for (int r = 0; r < PS; r++)
            cp_async8(&s_pix[r][c], &pixq[n0 + r * WIDTH]);
    }
    // Coefficients: 375 x 16B, contiguous in gmem.
    {
        const float4* gc = reinterpret_cast<const float4*>(coef + (size_t)patch0 * COEF_PER_PATCH);
        float4* sc = reinterpret_cast<float4*>(s_coef);
        #pragma unroll
        for (int i = threadIdx.x; i < COEF_VEC16; i += THREADS)
            cp_async16(sc + i, gc + i);
    }
    // Bias: 75 x 4B.
    if (threadIdx.x < PATCHES_PER_BLOCK * 3)
        cp_async4(&s_bias[threadIdx.x], &bias[patch0 * 3 + threadIdx.x]);

    asm volatile("cp.async.commit_group;\n cp.async.wait_group 0;" ::: "memory");
    __syncthreads();   // the ONLY long-latency wait in the kernel

    if (c >= COLS_PER_BLOCK) return;

    const int pl = c / PS;                        // local patch 0..24

    // Pixel pairs from smem (conflict-free LDS.64, lane-consecutive).
    ull xy[PS];
    #pragma unroll
    for (int r = 0; r < PS; r++)
        xy[r] = s_pix[r][c];

    #pragma unroll
    for (int ch = 0; ch < 3; ch++) {
        // 5 x LDS.128; lane stride 240B across ~7 patches/warp -> conflict-free.
        const ulonglong2* cfc =
            reinterpret_cast<const ulonglong2*>(s_coef) + pl * 15 + ch * 5;
        const ulonglong2 u0 = cfc[0];   // (c0, c1) pairs (a_t, b_t)
        const ulonglong2 u1 = cfc[1];
        const ulonglong2 u2 = cfc[2];
        const ulonglong2 u3 = cfc[3];
        const ulonglong2 u4 = cfc[4];
        const float bch = s_bias[pl * 3 + ch];

        // 5 independent packed Horner chains (one per row) -> ILP 5.
        #pragma unroll
        for (int r = 0; r < PS; r++) {
            ull h = u4.y;                  // (a9, b9)
            h = fma2(h, xy[r], u4.x);
            h = fma2(h, xy[r], u3.y);
            h = fma2(h, xy[r], u3.x);
            h = fma2(h, xy[r], u2.y);
            h = fma2(h, xy[r], u2.x);
            h = fma2(h, xy[r], u1.y);
            h = fma2(h, xy[r], u1.x);
            h = fma2(h, xy[r], u0.y);
            h = fma2(h, xy[r], u0.x);      // + (a0, b0)
            float hx, hy;
            unpack2(h, hx, hy);
            __stcs(&out[(size_t)ch * NPIX + n0 + r * WIDTH], hx + (hy + bch));
        }
    }
}

extern "C" void kernel_launch(void* const* d_in, const int* in_sizes, int n_in,
                              void* d_out, int out_size)
{
    const float* pix  = (const float*)d_in[0];   // [1e6, 2]
    const float* coef = (const float*)d_in[1];   // [40000, 3, 10, 2]
    const float* bias = (const float*)d_in[2];   // [40000, 3]
    float* out        = (float*)d_out;           // [3, 1e6]

    const int nblocks = (HEIGHT / PS) * SEGS;    // 200 * 8 = 1600
    ts_approx_kernel<<<nblocks, THREADS>>>(pix, coef, bias, out);
}